// round 3
// baseline (speedup 1.0000x reference)
#include <cuda_runtime.h>

#define N_ROWS 65536
#define A_DIM  512
#define C_CLS  1000
#define CAP    1024   // max rows per class stored (E[n]=65.5, sd 8 -> safe)

// ---- scratch (__device__ globals; zero-initialized at module load) ----
__device__ int g_nc[C_CLS];               // per-class count / scatter cursor
__device__ int g_bucket[C_CLS * CAP];     // row indices per class

// ---- stage 1: fused histogram + scatter (counting sort into buckets) ----
// int4 label loads: 4 labels per thread.
__global__ void k_bucket(const int4* __restrict__ labels4) {
    int i = blockIdx.x * blockDim.x + threadIdx.x;   // 0 .. N_ROWS/4-1
    int4 lb = labels4[i];
    int base = i * 4;
    int p;
    p = atomicAdd(&g_nc[lb.x], 1); if (p < CAP) g_bucket[lb.x * CAP + p] = base + 0;
    p = atomicAdd(&g_nc[lb.y], 1); if (p < CAP) g_bucket[lb.y * CAP + p] = base + 1;
    p = atomicAdd(&g_nc[lb.z], 1); if (p < CAP) g_bucket[lb.z * CAP + p] = base + 2;
    p = atomicAdd(&g_nc[lb.w], 1); if (p < CAP) g_bucket[lb.w * CAP + p] = base + 3;
}

// ---- stage 2: per-class reduce + fused finalize ----
// One block per class, 256 threads = 2 row-streams x 128 column lanes.
// Each lane owns a float4 (4 columns); each stream 4-row unrolled -> 4
// independent LDG.128 in flight per thread. Streams combined via smem.
__global__ void __launch_bounds__(256) k_main(
    const float* __restrict__ features,
    const float* __restrict__ count,
    const float* __restrict__ mean,
    const float* __restrict__ cov,
    float* __restrict__ out)
{
    const int c   = blockIdx.x;
    const int tid = threadIdx.x;
    const int r   = tid >> 7;          // row-stream 0/1
    const int col = tid & 127;         // float4 column index
    const int n = g_nc[c];
    const int n_eff = (n < CAP) ? n : CAP;

    __shared__ int rows[CAP];
    __shared__ float red_s[4 * 128];
    __shared__ float red_q[4 * 128];

    for (int j = tid; j < n_eff; j += 256) rows[j] = g_bucket[c * CAP + j];
    __syncthreads();
    if (tid == 0) g_nc[c] = 0;         // reset for next graph replay

    float4 s0 = make_float4(0.f, 0.f, 0.f, 0.f), s1 = s0;
    float4 q0 = s0, q1 = s0;

    const float4* __restrict__ f4 = (const float4*)features;

    // stream r handles rows r, r+2, r+4, ...; unroll 4 (stride 8)
    int j = r;
    for (; j + 6 < n_eff; j += 8) {
        float4 x0 = __ldg(&f4[rows[j + 0] * 128 + col]);
        float4 x1 = __ldg(&f4[rows[j + 2] * 128 + col]);
        float4 x2 = __ldg(&f4[rows[j + 4] * 128 + col]);
        float4 x3 = __ldg(&f4[rows[j + 6] * 128 + col]);
        s0.x += x0.x; s0.y += x0.y; s0.z += x0.z; s0.w += x0.w;
        q0.x = fmaf(x0.x, x0.x, q0.x); q0.y = fmaf(x0.y, x0.y, q0.y);
        q0.z = fmaf(x0.z, x0.z, q0.z); q0.w = fmaf(x0.w, x0.w, q0.w);
        s1.x += x1.x; s1.y += x1.y; s1.z += x1.z; s1.w += x1.w;
        q1.x = fmaf(x1.x, x1.x, q1.x); q1.y = fmaf(x1.y, x1.y, q1.y);
        q1.z = fmaf(x1.z, x1.z, q1.z); q1.w = fmaf(x1.w, x1.w, q1.w);
        s0.x += x2.x; s0.y += x2.y; s0.z += x2.z; s0.w += x2.w;
        q0.x = fmaf(x2.x, x2.x, q0.x); q0.y = fmaf(x2.y, x2.y, q0.y);
        q0.z = fmaf(x2.z, x2.z, q0.z); q0.w = fmaf(x2.w, x2.w, q0.w);
        s1.x += x3.x; s1.y += x3.y; s1.z += x3.z; s1.w += x3.w;
        q1.x = fmaf(x3.x, x3.x, q1.x); q1.y = fmaf(x3.y, x3.y, q1.y);
        q1.z = fmaf(x3.z, x3.z, q1.z); q1.w = fmaf(x3.w, x3.w, q1.w);
    }
    for (; j < n_eff; j += 2) {
        float4 x = __ldg(&f4[rows[j] * 128 + col]);
        s0.x += x.x; s0.y += x.y; s0.z += x.z; s0.w += x.w;
        q0.x = fmaf(x.x, x.x, q0.x); q0.y = fmaf(x.y, x.y, q0.y);
        q0.z = fmaf(x.z, x.z, q0.z); q0.w = fmaf(x.w, x.w, q0.w);
    }

    float4 s = make_float4(s0.x + s1.x, s0.y + s1.y, s0.z + s1.z, s0.w + s1.w);
    float4 q = make_float4(q0.x + q1.x, q0.y + q1.y, q0.z + q1.z, q0.w + q1.w);

    // combine the two row-streams through smem
    if (r == 1) {
        red_s[col * 4 + 0] = s.x; red_s[col * 4 + 1] = s.y;
        red_s[col * 4 + 2] = s.z; red_s[col * 4 + 3] = s.w;
        red_q[col * 4 + 0] = q.x; red_q[col * 4 + 1] = q.y;
        red_q[col * 4 + 2] = q.z; red_q[col * 4 + 3] = q.w;
    }
    __syncthreads();
    if (r == 1) return;

    s.x += red_s[col * 4 + 0]; s.y += red_s[col * 4 + 1];
    s.z += red_s[col * 4 + 2]; s.w += red_s[col * 4 + 3];
    q.x += red_q[col * 4 + 0]; q.y += red_q[col * 4 + 1];
    q.z += red_q[col * 4 + 2]; q.w += red_q[col * 4 + 3];

    const float fn    = (float)n;
    const float amt   = (n == 0) ? 1.0f : fn;
    const float inv   = 1.0f / amt;
    const float cnt_c = count[c];
    const float denom = fn + cnt_c;
    const float w     = (denom == 0.0f) ? 0.0f : fn / denom;
    const float omw   = 1.0f - w;
    const float wow   = w * omw;

    const int idx = c * A_DIM + col * 4;
    const float4 m4  = __ldg((const float4*)(mean + idx));
    const float4 cv4 = __ldg((const float4*)(cov + idx));

    float4 cov_new, mean_new;
    {
        float ave = s.x * inv; float var = fmaf(-ave, ave, q.x * inv);
        float d = m4.x - ave;
        cov_new.x  = cv4.x * omw + var * w + wow * d * d;
        mean_new.x = m4.x * omw + ave * w;
    }
    {
        float ave = s.y * inv; float var = fmaf(-ave, ave, q.y * inv);
        float d = m4.y - ave;
        cov_new.y  = cv4.y * omw + var * w + wow * d * d;
        mean_new.y = m4.y * omw + ave * w;
    }
    {
        float ave = s.z * inv; float var = fmaf(-ave, ave, q.z * inv);
        float d = m4.z - ave;
        cov_new.z  = cv4.z * omw + var * w + wow * d * d;
        mean_new.z = m4.z * omw + ave * w;
    }
    {
        float ave = s.w * inv; float var = fmaf(-ave, ave, q.w * inv);
        float d = m4.w - ave;
        cov_new.w  = cv4.w * omw + var * w + wow * d * d;
        mean_new.w = m4.w * omw + ave * w;
    }

    *(float4*)(out + idx) = cov_new;                          // cov_new  [C*A]
    *(float4*)(out + C_CLS * A_DIM + idx) = mean_new;         // mean_new [C*A]
    if (col == 0) out[2 * C_CLS * A_DIM + c] = cnt_c + fn;    // count_new [C]
}

extern "C" void kernel_launch(void* const* d_in, const int* in_sizes, int n_in,
                              void* d_out, int out_size) {
    const float* features = (const float*)d_in[0];
    const int*   labels   = (const int*)  d_in[1];
    const float* count    = (const float*)d_in[2];
    const float* mean     = (const float*)d_in[3];
    const float* cov      = (const float*)d_in[4];
    float* out = (float*)d_out;

    (void)in_sizes; (void)n_in; (void)out_size;

    k_bucket<<<N_ROWS / 4 / 256, 256>>>((const int4*)labels);
    k_main<<<C_CLS, 256>>>(features, count, mean, cov, out);
}